// round 1
// baseline (speedup 1.0000x reference)
#include <cuda_runtime.h>
#include <math.h>

#define SLEN 2048
#define BATCH 64
#define DIN 512
#define DSRC 512
#define DAL 512
#define NTOK (SLEN * BATCH)   // 131072
#define CTX_ELEMS (BATCH * DSRC)  // 32768

// Scratch (no cudaMalloc allowed)
__device__ float g_q[BATCH * DAL];      // input @ W1[:, :512]^T + b1   [B, DAL]
__device__ float g_scores[NTOK];        // pre-softmax scores           [S*B]

// ---------------------------------------------------------------------------
// Kernel Q: g_q[b][a] = sum_k input[b,k] * W1[a,k] + b1[a]
// One warp per output element (32768 warps), coalesced over k.
// ---------------------------------------------------------------------------
__global__ __launch_bounds__(256) void k_q(const float* __restrict__ inp,
                                           const float* __restrict__ W1,
                                           const float* __restrict__ b1) {
    int gw = blockIdx.x * 8 + (threadIdx.x >> 5);
    int lane = threadIdx.x & 31;
    int b = gw >> 9;        // / 512
    int a = gw & 511;
    const float* ip = inp + b * DIN;
    const float* wp = W1 + (size_t)a * (DIN + DSRC);
    float s = 0.f;
    #pragma unroll 4
    for (int k = lane; k < DIN; k += 32) s += ip[k] * wp[k];
    #pragma unroll
    for (int o = 16; o; o >>= 1) s += __shfl_xor_sync(0xFFFFFFFFu, s, o);
    if (lane == 0) g_q[b * DAL + a] = s + b1[a];
}

// ---------------------------------------------------------------------------
// Kernel init: scores[t] = b2[0]
// ---------------------------------------------------------------------------
__global__ void k_init_scores(const float* __restrict__ b2) {
    int i = blockIdx.x * blockDim.x + threadIdx.x;
    if (i < NTOK) g_scores[i] = b2[0];
}

// ---------------------------------------------------------------------------
// Kernel GEMM+score: for token tile [64] x align tile [128]:
//   acc = src_tile @ W1src_tile^T   (K = 512)
//   partial_score[t] = sum_col W2[col] * tanh(acc + g_q[b, col])
//   atomicAdd into g_scores[t]
// ---------------------------------------------------------------------------
__global__ __launch_bounds__(256) void k_gemm(const float* __restrict__ src,
                                              const float* __restrict__ W1,
                                              const float* __restrict__ W2) {
    __shared__ float As[16][68];    // [k][m], padded
    __shared__ float Bs[16][132];   // [k][n], padded
    __shared__ float red[64][17];   // per-token partial-score reduction

    const int t0 = blockIdx.x * 64;
    const int n0 = blockIdx.y * 128;
    const int tid = threadIdx.x;

    float acc[4][8];
    #pragma unroll
    for (int i = 0; i < 4; i++)
        #pragma unroll
        for (int j = 0; j < 8; j++) acc[i][j] = 0.f;

    const int arow = tid >> 2;      // 0..63
    const int aq   = tid & 3;       // 0..3

    for (int kk = 0; kk < 512; kk += 16) {
        // Load A tile: 64 tokens x 16 k (float4 per thread)
        float4 av = *reinterpret_cast<const float4*>(
            src + (size_t)(t0 + arow) * DSRC + kk + aq * 4);
        As[aq * 4 + 0][arow] = av.x;
        As[aq * 4 + 1][arow] = av.y;
        As[aq * 4 + 2][arow] = av.z;
        As[aq * 4 + 3][arow] = av.w;

        // Load B tile: 128 aligns x 16 k (2 float4 per thread)
        #pragma unroll
        for (int j = 0; j < 2; j++) {
            int row = arow + j * 64;          // 0..127
            float4 bv = *reinterpret_cast<const float4*>(
                W1 + (size_t)(n0 + row) * (DIN + DSRC) + DIN + kk + aq * 4);
            Bs[aq * 4 + 0][row] = bv.x;
            Bs[aq * 4 + 1][row] = bv.y;
            Bs[aq * 4 + 2][row] = bv.z;
            Bs[aq * 4 + 3][row] = bv.w;
        }
        __syncthreads();

        const int tm = (tid & 15) * 4;
        const int tn = (tid >> 4) * 8;
        #pragma unroll
        for (int k = 0; k < 16; k++) {
            float4 a4 = *reinterpret_cast<float4*>(&As[k][tm]);
            float4 b0 = *reinterpret_cast<float4*>(&Bs[k][tn]);
            float4 b1v = *reinterpret_cast<float4*>(&Bs[k][tn + 4]);
            float am[4] = {a4.x, a4.y, a4.z, a4.w};
            float bn[8] = {b0.x, b0.y, b0.z, b0.w, b1v.x, b1v.y, b1v.z, b1v.w};
            #pragma unroll
            for (int mi = 0; mi < 4; mi++)
                #pragma unroll
                for (int ni = 0; ni < 8; ni++)
                    acc[mi][ni] += am[mi] * bn[ni];
        }
        __syncthreads();
    }

    // Epilogue: tanh + W2 dot, reduce over the 128 aligns of this tile
    const int tm = (tid & 15) * 4;
    const int tn = (tid >> 4) * 8;
    float w2l[8];
    #pragma unroll
    for (int ni = 0; ni < 8; ni++) w2l[ni] = W2[n0 + tn + ni];

    #pragma unroll
    for (int mi = 0; mi < 4; mi++) {
        int t = t0 + tm + mi;
        int bb = t & (BATCH - 1);
        const float* qrow = g_q + bb * DAL + n0 + tn;
        float p = 0.f;
        #pragma unroll
        for (int ni = 0; ni < 8; ni++)
            p += w2l[ni] * tanhf(acc[mi][ni] + qrow[ni]);
        red[tm + mi][tid >> 4] = p;
    }
    __syncthreads();
    if (tid < 64) {
        float s = 0.f;
        #pragma unroll
        for (int j = 0; j < 16; j++) s += red[tid][j];
        atomicAdd(&g_scores[t0 + tid], s);
    }
}

// ---------------------------------------------------------------------------
// Kernel softmax: per b, softmax over S. Writes attn to out[CTX_ELEMS + s*B + b].
// ---------------------------------------------------------------------------
__global__ __launch_bounds__(256) void k_softmax(const unsigned char* __restrict__ mask,
                                                 float* __restrict__ out) {
    const int b = blockIdx.x;
    const int tid = threadIdx.x;
    __shared__ float red[256];

    float lmax = -INFINITY;
    for (int s = tid; s < SLEN; s += 256) {
        float v = mask[s * BATCH + b] ? -INFINITY : g_scores[s * BATCH + b];
        lmax = fmaxf(lmax, v);
    }
    red[tid] = lmax; __syncthreads();
    for (int o = 128; o; o >>= 1) {
        if (tid < o) red[tid] = fmaxf(red[tid], red[tid + o]);
        __syncthreads();
    }
    float m = red[0]; __syncthreads();

    float lsum = 0.f;
    for (int s = tid; s < SLEN; s += 256) {
        float v = mask[s * BATCH + b] ? -INFINITY : g_scores[s * BATCH + b];
        lsum += expf(v - m);
    }
    red[tid] = lsum; __syncthreads();
    for (int o = 128; o; o >>= 1) {
        if (tid < o) red[tid] += red[tid + o];
        __syncthreads();
    }
    float inv = 1.f / red[0];

    for (int s = tid; s < SLEN; s += 256) {
        float v = mask[s * BATCH + b] ? -INFINITY : g_scores[s * BATCH + b];
        out[CTX_ELEMS + s * BATCH + b] = expf(v - m) * inv;
    }
}

// ---------------------------------------------------------------------------
// Kernel ctx: ctx[b, d] = sum_s attn[s, b] * src[s, b, d]
// grid (B, 8 s-chunks), 256 threads (float2 per thread over d).
// ctx region of out is pre-zeroed by cudaMemsetAsync; atomicAdd partials.
// ---------------------------------------------------------------------------
__global__ __launch_bounds__(256) void k_ctx(const float* __restrict__ src,
                                             float* __restrict__ out) {
    const int b = blockIdx.x;
    const int c = blockIdx.y;
    const int tid = threadIdx.x;
    const float* attn = out + CTX_ELEMS;

    float ax = 0.f, ay = 0.f;
    const int s_begin = c * (SLEN / 8);
    const int s_end = s_begin + (SLEN / 8);
    for (int s = s_begin; s < s_end; s++) {
        float a = attn[s * BATCH + b];
        float2 v = *reinterpret_cast<const float2*>(
            src + (size_t)(s * BATCH + b) * DSRC + tid * 2);
        ax += a * v.x;
        ay += a * v.y;
    }
    atomicAdd(&out[b * DSRC + tid * 2 + 0], ax);
    atomicAdd(&out[b * DSRC + tid * 2 + 1], ay);
}

// ---------------------------------------------------------------------------
extern "C" void kernel_launch(void* const* d_in, const int* in_sizes, int n_in,
                              void* d_out, int out_size) {
    const float* inp = (const float*)d_in[0];
    const float* src = (const float*)d_in[1];
    const unsigned char* mask = (const unsigned char*)d_in[2];
    const float* W1 = (const float*)d_in[3];
    const float* b1 = (const float*)d_in[4];
    const float* W2 = (const float*)d_in[5];
    const float* b2 = (const float*)d_in[6];
    float* out = (float*)d_out;

    // Zero the ctx region (out is poisoned); attn region is fully overwritten.
    cudaMemsetAsync(out, 0, CTX_ELEMS * sizeof(float), 0);

    k_q<<<4096, 256>>>(inp, W1, b1);
    k_init_scores<<<NTOK / 256, 256>>>(b2);

    dim3 gg(NTOK / 64, DAL / 128);
    k_gemm<<<gg, 256>>>(src, W1, W2);

    k_softmax<<<BATCH, 256>>>(mask, out);

    k_ctx<<<dim3(BATCH, 8), 256>>>(src, out);
}

// round 5
// speedup vs baseline: 2.0782x; 2.0782x over previous
#include <cuda_runtime.h>
#include <cuda_bf16.h>
#include <math.h>
#include <stdint.h>

#define SLEN 2048
#define BATCH 64
#define DIN 512
#define DSRC 512
#define DAL 512
#define NTOK (SLEN * BATCH)       // 131072
#define CTX_ELEMS (BATCH * DSRC)  // 32768

// ---------------------------------------------------------------------------
// Scratch (__device__ globals; no cudaMalloc allowed)
// ---------------------------------------------------------------------------
__device__ float g_q[BATCH * DAL];            // input@W1[:, :512]^T + b1
__device__ float g_part[4 * NTOK];            // per-n-tile partial scores [nt][b][s]

// ---------------------------------------------------------------------------
// Helpers
// ---------------------------------------------------------------------------
__device__ __forceinline__ uint32_t smem_u32(const void* p) {
    uint32_t a;
    asm("{ .reg .u64 t; cvta.to.shared.u64 t, %1; cvt.u32.u64 %0, t; }" : "=r"(a) : "l"(p));
    return a;
}

__device__ __forceinline__ void ldsm4(uint32_t* r, uint32_t addr) {
    asm volatile("ldmatrix.sync.aligned.m8n8.x4.shared.b16 {%0,%1,%2,%3}, [%4];"
                 : "=r"(r[0]), "=r"(r[1]), "=r"(r[2]), "=r"(r[3]) : "r"(addr));
}

__device__ __forceinline__ void mma_bf16(float* d, const uint32_t* a, const uint32_t* b) {
    asm volatile("mma.sync.aligned.m16n8k16.row.col.f32.bf16.bf16.f32 "
                 "{%0,%1,%2,%3}, {%4,%5,%6,%7}, {%8,%9}, {%0,%1,%2,%3};"
                 : "+f"(d[0]), "+f"(d[1]), "+f"(d[2]), "+f"(d[3])
                 : "r"(a[0]), "r"(a[1]), "r"(a[2]), "r"(a[3]), "r"(b[0]), "r"(b[1]));
}

// fp32 pair -> bf16 hi pair (packed) + bf16 lo (residual) pair
__device__ __forceinline__ uint32_t pack_hi2(float a, float b, uint32_t& lo) {
    __nv_bfloat16 ha = __float2bfloat16(a), hb = __float2bfloat16(b);
    float fa = __bfloat162float(ha), fb = __bfloat162float(hb);
    __nv_bfloat16 la = __float2bfloat16(a - fa), lb = __float2bfloat16(b - fb);
    lo = (uint32_t)__bfloat16_as_ushort(la) | ((uint32_t)__bfloat16_as_ushort(lb) << 16);
    return (uint32_t)__bfloat16_as_ushort(ha) | ((uint32_t)__bfloat16_as_ushort(hb) << 16);
}

__device__ __forceinline__ void cvt8(const float4 v0, const float4 v1, uint4& h, uint4& l) {
    h.x = pack_hi2(v0.x, v0.y, l.x);
    h.y = pack_hi2(v0.z, v0.w, l.y);
    h.z = pack_hi2(v1.x, v1.y, l.z);
    h.w = pack_hi2(v1.z, v1.w, l.w);
}

// ---------------------------------------------------------------------------
// Pre-kernel: g_q[b][a] = input[b,:] . W1[a, :512] + b1[a]
// ---------------------------------------------------------------------------
__global__ __launch_bounds__(256) void k_q(const float* __restrict__ inp,
                                           const float* __restrict__ W1,
                                           const float* __restrict__ b1) {
    int gw = blockIdx.x * 8 + (threadIdx.x >> 5);
    int lane = threadIdx.x & 31;
    int b = gw >> 9, a = gw & 511;
    const float* ip = inp + b * DIN;
    const float* wp = W1 + (size_t)a * (DIN + DSRC);
    float s = 0.f;
    #pragma unroll 4
    for (int k = lane; k < DIN; k += 32) s += ip[k] * wp[k];
    #pragma unroll
    for (int o = 16; o; o >>= 1) s += __shfl_xor_sync(0xFFFFFFFFu, s, o);
    if (lane == 0) g_q[b * DAL + a] = s + b1[a];
}

// ---------------------------------------------------------------------------
// Main HMMA kernel. CTA: M=128 tokens x N=128 aligns, K=512 in 16 chunks of 32.
// smem rows: 128 rows x 80B stride (64B bf16 data + 16B pad) -> conflict-free
// ldmatrix (slot = (5*row + seg) mod 8 is a permutation).
// 8 warps: warp_m = wid&3 (32 rows), warp_n = wid>>2 (64 cols).
// D = Ahi.Bhi + Ahi.Blo + Alo.Bhi (fp32 accum in registers).
// Epilogue: partial_score[t] = sum_{n in tile} W2[n]*tanh(D + q[b][n])
//           -> g_part[blockIdx.y][b][s]   (deterministic, no atomics)
// ---------------------------------------------------------------------------
#define ROWB 80
#define BUF_AH 0
#define BUF_AL 10240
#define BUF_BH 20480
#define BUF_BL 30720
#define STAGE_SZ 40960
#define S_QS   81920                      // 64 x 132 floats = 33792
#define S_W2   (S_QS + 33792)             // 128 floats
#define S_RED  (S_W2 + 512)               // 128 x 2 floats
#define SMEM_TOTAL (S_RED + 1024)         // 117248

__global__ __launch_bounds__(256, 1) void k_main(const float* __restrict__ src,
                                                 const float* __restrict__ W1,
                                                 const float* __restrict__ W2) {
    extern __shared__ __align__(16) char smem[];
    const uint32_t sb = smem_u32(smem);
    const int tid = threadIdx.x;
    const int lane = tid & 31;
    const int wid = tid >> 5;
    const int warp_m = wid & 3;
    const int warp_n = wid >> 2;
    const int t0 = blockIdx.x * 128;
    const int n0 = blockIdx.y * 128;

    // Staging unit mapping: unit u in [0,512): row = u>>2, seg j = u&3 (8 fp32)
    const int u0 = tid, u1 = tid + 256;
    const int r0 = u0 >> 2, j0 = u0 & 3;
    const int r1 = u1 >> 2, j1 = u1 & 3;

    float acc[2][8][4];
    #pragma unroll
    for (int mt = 0; mt < 2; mt++)
        #pragma unroll
        for (int nt = 0; nt < 8; nt++)
            #pragma unroll
            for (int c = 0; c < 4; c++) acc[mt][nt][c] = 0.f;

    // Stage W2 tile
    if (tid < 128) ((float*)(smem + S_W2))[tid] = W2[n0 + tid];

    // Prologue: chunk 0 -> stage 0
    {
        const float* pa0 = src + (size_t)(t0 + r0) * DSRC + j0 * 8;
        const float* pa1 = src + (size_t)(t0 + r1) * DSRC + j1 * 8;
        const float* pb0 = W1 + (size_t)(n0 + r0) * (DIN + DSRC) + DIN + j0 * 8;
        const float* pb1 = W1 + (size_t)(n0 + r1) * (DIN + DSRC) + DIN + j1 * 8;
        uint4 h, l;
        cvt8(*(const float4*)pa0, *(const float4*)(pa0 + 4), h, l);
        *(uint4*)(smem + BUF_AH + r0 * ROWB + j0 * 16) = h;
        *(uint4*)(smem + BUF_AL + r0 * ROWB + j0 * 16) = l;
        cvt8(*(const float4*)pa1, *(const float4*)(pa1 + 4), h, l);
        *(uint4*)(smem + BUF_AH + r1 * ROWB + j1 * 16) = h;
        *(uint4*)(smem + BUF_AL + r1 * ROWB + j1 * 16) = l;
        cvt8(*(const float4*)pb0, *(const float4*)(pb0 + 4), h, l);
        *(uint4*)(smem + BUF_BH + r0 * ROWB + j0 * 16) = h;
        *(uint4*)(smem + BUF_BL + r0 * ROWB + j0 * 16) = l;
        cvt8(*(const float4*)pb1, *(const float4*)(pb1 + 4), h, l);
        *(uint4*)(smem + BUF_BH + r1 * ROWB + j1 * 16) = h;
        *(uint4*)(smem + BUF_BL + r1 * ROWB + j1 * 16) = l;
    }
    __syncthreads();

    // ldmatrix lane-address components (fixed per thread)
    const uint32_t a_row = warp_m * 32 + (lane & 15);
    const uint32_t a_kadd = (lane >> 4) * 16;
    const uint32_t b_row = warp_n * 64 + (lane & 7) + ((lane >> 4) & 1) * 8;
    const uint32_t b_kadd = ((lane >> 3) & 1) * 16;

    for (int kc = 0; kc < 16; kc++) {
        const uint32_t st = sb + (kc & 1) * STAGE_SZ;

        // Prefetch next chunk into registers (global loads issue early)
        float4 va00, va01, va10, va11, vb00, vb01, vb10, vb11;
        if (kc + 1 < 16) {
            const int ko = (kc + 1) * 32;
            const float* pa0 = src + (size_t)(t0 + r0) * DSRC + ko + j0 * 8;
            const float* pa1 = src + (size_t)(t0 + r1) * DSRC + ko + j1 * 8;
            const float* pb0 = W1 + (size_t)(n0 + r0) * (DIN + DSRC) + DIN + ko + j0 * 8;
            const float* pb1 = W1 + (size_t)(n0 + r1) * (DIN + DSRC) + DIN + ko + j1 * 8;
            va00 = *(const float4*)pa0; va01 = *(const float4*)(pa0 + 4);
            va10 = *(const float4*)pa1; va11 = *(const float4*)(pa1 + 4);
            vb00 = *(const float4*)pb0; vb01 = *(const float4*)(pb0 + 4);
            vb10 = *(const float4*)pb1; vb11 = *(const float4*)(pb1 + 4);
        }

        // Compute: 2 k16 steps on stage kc&1
        #pragma unroll
        for (int ks = 0; ks < 2; ks++) {
            const uint32_t koff = ks * 32;
            uint32_t ahi[2][4], alo[2][4];
            #pragma unroll
            for (int mt = 0; mt < 2; mt++) {
                uint32_t ra = (a_row + mt * 16) * ROWB + koff + a_kadd;
                ldsm4(ahi[mt], st + BUF_AH + ra);
                ldsm4(alo[mt], st + BUF_AL + ra);
            }
            #pragma unroll
            for (int np = 0; np < 4; np++) {
                uint32_t rb = (b_row + np * 16) * ROWB + koff + b_kadd;
                uint32_t bh[4], bl[4];
                ldsm4(bh, st + BUF_BH + rb);
                ldsm4(bl, st + BUF_BL + rb);
                #pragma unroll
                for (int mt = 0; mt < 2; mt++) {
                    #pragma unroll
                    for (int sub = 0; sub < 2; sub++) {
                        float* d = acc[mt][np * 2 + sub];
                        mma_bf16(d, ahi[mt], &bh[sub * 2]);
                        mma_bf16(d, ahi[mt], &bl[sub * 2]);
                        mma_bf16(d, alo[mt], &bh[sub * 2]);
                    }
                }
            }
        }

        // Store prefetched chunk into the other stage
        if (kc + 1 < 16) {
            char* dst = smem + ((kc + 1) & 1) * STAGE_SZ;
            uint4 h, l;
            cvt8(va00, va01, h, l);
            *(uint4*)(dst + BUF_AH + r0 * ROWB + j0 * 16) = h;
            *(uint4*)(dst + BUF_AL + r0 * ROWB + j0 * 16) = l;
            cvt8(va10, va11, h, l);
            *(uint4*)(dst + BUF_AH + r1 * ROWB + j1 * 16) = h;
            *(uint4*)(dst + BUF_AL + r1 * ROWB + j1 * 16) = l;
            cvt8(vb00, vb01, h, l);
            *(uint4*)(dst + BUF_BH + r0 * ROWB + j0 * 16) = h;
            *(uint4*)(dst + BUF_BL + r0 * ROWB + j0 * 16) = l;
            cvt8(vb10, vb11, h, l);
            *(uint4*)(dst + BUF_BH + r1 * ROWB + j1 * 16) = h;
            *(uint4*)(dst + BUF_BL + r1 * ROWB + j1 * 16) = l;
        }
        __syncthreads();
    }

    // Stage q[b][n0..n0+127] into smem (pad-132 rows)
    float* qs = (float*)(smem + S_QS);
    #pragma unroll
    for (int i = 0; i < 8; i++) {
        int unit = tid + i * 256;         // 2048 float4 units
        int b = unit >> 5, c4 = unit & 31;
        float4 v = *(const float4*)(g_q + b * DAL + n0 + c4 * 4);
        float* d = qs + b * 132 + c4 * 4;
        d[0] = v.x; d[1] = v.y; d[2] = v.z; d[3] = v.w;
    }
    __syncthreads();

    // Epilogue: per-thread tanh + W2 dot, quad-reduce, cross-warp_n combine
    {
        const float* w2s = (const float*)(smem + S_W2);
        float* red = (float*)(smem + S_RED);
        float p[2][2] = {{0.f, 0.f}, {0.f, 0.f}};
        const int colq = 2 * (lane & 3);
        #pragma unroll
        for (int mt = 0; mt < 2; mt++) {
            #pragma unroll
            for (int nt = 0; nt < 8; nt++) {
                int nloc = warp_n * 64 + nt * 8 + colq;
                float w2a = w2s[nloc], w2b = w2s[nloc + 1];
                #pragma unroll
                for (int h = 0; h < 2; h++) {
                    int rowloc = warp_m * 32 + mt * 16 + h * 8 + (lane >> 2);
                    int b = rowloc & 63;
                    float q0 = qs[b * 132 + nloc];
                    float q1 = qs[b * 132 + nloc + 1];
                    p[mt][h] += w2a * tanhf(acc[mt][nt][h * 2 + 0] + q0)
                              + w2b * tanhf(acc[mt][nt][h * 2 + 1] + q1);
                }
            }
        }
        #pragma unroll
        for (int mt = 0; mt < 2; mt++)
            #pragma unroll
            for (int h = 0; h < 2; h++) {
                p[mt][h] += __shfl_xor_sync(0xFFFFFFFFu, p[mt][h], 1);
                p[mt][h] += __shfl_xor_sync(0xFFFFFFFFu, p[mt][h], 2);
            }
        if ((lane & 3) == 0) {
            #pragma unroll
            for (int mt = 0; mt < 2; mt++)
                #pragma unroll
                for (int h = 0; h < 2; h++) {
                    int rowloc = warp_m * 32 + mt * 16 + h * 8 + (lane >> 2);
                    red[rowloc * 2 + warp_n] = p[mt][h];
                }
        }
        __syncthreads();
        if (tid < 128) {
            int t = t0 + tid;
            g_part[blockIdx.y * NTOK + (t & 63) * SLEN + (t >> 6)] =
                red[tid * 2] + red[tid * 2 + 1];
        }
    }
}

// ---------------------------------------------------------------------------
// Softmax over S per batch; sums the 4 n-tile partials; attn -> out[CTX + s*B + b]
// ---------------------------------------------------------------------------
__global__ __launch_bounds__(256) void k_softmax(const unsigned char* __restrict__ mask,
                                                 float* __restrict__ out) {
    const int b = blockIdx.x;
    const int tid = threadIdx.x;
    __shared__ float red[256];
    const float* p0 = g_part + 0 * NTOK + b * SLEN;
    const float* p1 = g_part + 1 * NTOK + b * SLEN;
    const float* p2 = g_part + 2 * NTOK + b * SLEN;
    const float* p3 = g_part + 3 * NTOK + b * SLEN;

    float lmax = -INFINITY;
    for (int s = tid; s < SLEN; s += 256) {
        float v = mask[s * BATCH + b] ? -INFINITY : (p0[s] + p1[s] + p2[s] + p3[s]);
        lmax = fmaxf(lmax, v);
    }
    red[tid] = lmax; __syncthreads();
    for (int o = 128; o; o >>= 1) {
        if (tid < o) red[tid] = fmaxf(red[tid], red[tid + o]);
        __syncthreads();
    }
    float m = red[0]; __syncthreads();

    float lsum = 0.f;
    for (int s = tid; s < SLEN; s += 256) {
        float v = mask[s * BATCH + b] ? -INFINITY : (p0[s] + p1[s] + p2[s] + p3[s]);
        lsum += expf(v - m);
    }
    red[tid] = lsum; __syncthreads();
    for (int o = 128; o; o >>= 1) {
        if (tid < o) red[tid] += red[tid + o];
        __syncthreads();
    }
    float inv = 1.f / red[0];

    for (int s = tid; s < SLEN; s += 256) {
        float v = mask[s * BATCH + b] ? -INFINITY : (p0[s] + p1[s] + p2[s] + p3[s]);
        out[CTX_ELEMS + s * BATCH + b] = expf(v - m) * inv;
    }
}

// ---------------------------------------------------------------------------
// ctx[b, d] = sum_s attn[s, b] * src[s, b, d]   (split-S, atomic merge)
// ---------------------------------------------------------------------------
__global__ __launch_bounds__(256) void k_ctx(const float* __restrict__ src,
                                             float* __restrict__ out) {
    const int b = blockIdx.x;
    const int c = blockIdx.y;
    const int tid = threadIdx.x;
    const float* attn = out + CTX_ELEMS;

    float ax = 0.f, ay = 0.f;
    const int s_begin = c * (SLEN / 8);
    const int s_end = s_begin + (SLEN / 8);
    for (int s = s_begin; s < s_end; s += 2) {
        float a0 = attn[s * BATCH + b];
        float a1 = attn[(s + 1) * BATCH + b];
        float2 v0 = *reinterpret_cast<const float2*>(
            src + (size_t)(s * BATCH + b) * DSRC + tid * 2);
        float2 v1 = *reinterpret_cast<const float2*>(
            src + (size_t)((s + 1) * BATCH + b) * DSRC + tid * 2);
        ax += a0 * v0.x + a1 * v1.x;
        ay += a0 * v0.y + a1 * v1.y;
    }
    atomicAdd(&out[b * DSRC + tid * 2 + 0], ax);
    atomicAdd(&out[b * DSRC + tid * 2 + 1], ay);
}

// ---------------------------------------------------------------------------
extern "C" void kernel_launch(void* const* d_in, const int* in_sizes, int n_in,
                              void* d_out, int out_size) {
    const float* inp = (const float*)d_in[0];
    const float* src = (const float*)d_in[1];
    const unsigned char* mask = (const unsigned char*)d_in[2];
    const float* W1 = (const float*)d_in[3];
    const float* b1 = (const float*)d_in[4];
    const float* W2 = (const float*)d_in[5];
    float* out = (float*)d_out;

    cudaFuncSetAttribute(k_main, cudaFuncAttributeMaxDynamicSharedMemorySize, SMEM_TOTAL);

    cudaMemsetAsync(out, 0, CTX_ELEMS * sizeof(float), 0);

    k_q<<<4096, 256>>>(inp, W1, b1);

    dim3 gg(NTOK / 128, DAL / 128);
    k_main<<<gg, 256, SMEM_TOTAL>>>(src, W1, W2);

    k_softmax<<<BATCH, 256>>>(mask, out);
    k_ctx<<<dim3(BATCH, 8), 256>>>(src, out);
}

// round 6
// speedup vs baseline: 2.7426x; 1.3197x over previous
#include <cuda_runtime.h>
#include <cuda_bf16.h>
#include <math.h>
#include <stdint.h>

#define SLEN 2048
#define BATCH 64
#define DIN 512
#define DSRC 512
#define DAL 512
#define NTOK (SLEN * BATCH)       // 131072
#define CTX_ELEMS (BATCH * DSRC)  // 32768

// ---------------------------------------------------------------------------
// Scratch (__device__ globals; no cudaMalloc allowed)
// ---------------------------------------------------------------------------
__device__ float g_q[BATCH * DAL];                 // input@W1[:, :512]^T + b1
__device__ float g_part[4 * NTOK];                 // per-n-tile partial scores [nt][b][s]
__device__ __nv_bfloat16 g_Ahi[(size_t)NTOK * DSRC];   // src hi  (128MB)
__device__ __nv_bfloat16 g_Alo[(size_t)NTOK * DSRC];   // src lo  (128MB)
__device__ __nv_bfloat16 g_Bhi[DAL * DSRC];            // W1 src-half hi
__device__ __nv_bfloat16 g_Blo[DAL * DSRC];            // W1 src-half lo

// ---------------------------------------------------------------------------
// Helpers
// ---------------------------------------------------------------------------
#define SW64(o) ((o) ^ (((o) >> 3) & 0x30))

__device__ __forceinline__ uint32_t smem_u32(const void* p) {
    uint32_t a;
    asm("{ .reg .u64 t; cvta.to.shared.u64 t, %1; cvt.u32.u64 %0, t; }" : "=r"(a) : "l"(p));
    return a;
}
#define CP16(dst, src) \
    asm volatile("cp.async.cg.shared.global [%0], [%1], 16;" :: "r"(dst), "l"(src))
#define CP_COMMIT() asm volatile("cp.async.commit_group;" ::: "memory")
#define CP_WAIT1() asm volatile("cp.async.wait_group 1;" ::: "memory")
#define CP_WAIT0() asm volatile("cp.async.wait_group 0;" ::: "memory")

__device__ __forceinline__ void ldsm4(uint32_t* r, uint32_t addr) {
    asm volatile("ldmatrix.sync.aligned.m8n8.x4.shared.b16 {%0,%1,%2,%3}, [%4];"
                 : "=r"(r[0]), "=r"(r[1]), "=r"(r[2]), "=r"(r[3]) : "r"(addr));
}
__device__ __forceinline__ void mma_bf16(float* d, const uint32_t* a, const uint32_t* b) {
    asm volatile("mma.sync.aligned.m16n8k16.row.col.f32.bf16.bf16.f32 "
                 "{%0,%1,%2,%3}, {%4,%5,%6,%7}, {%8,%9}, {%0,%1,%2,%3};"
                 : "+f"(d[0]), "+f"(d[1]), "+f"(d[2]), "+f"(d[3])
                 : "r"(a[0]), "r"(a[1]), "r"(a[2]), "r"(a[3]), "r"(b[0]), "r"(b[1]));
}
__device__ __forceinline__ uint32_t pack_hi2(float a, float b, uint32_t& lo) {
    __nv_bfloat16 ha = __float2bfloat16(a), hb = __float2bfloat16(b);
    float fa = __bfloat162float(ha), fb = __bfloat162float(hb);
    __nv_bfloat16 la = __float2bfloat16(a - fa), lb = __float2bfloat16(b - fb);
    lo = (uint32_t)__bfloat16_as_ushort(la) | ((uint32_t)__bfloat16_as_ushort(lb) << 16);
    return (uint32_t)__bfloat16_as_ushort(ha) | ((uint32_t)__bfloat16_as_ushort(hb) << 16);
}
__device__ __forceinline__ void cvt8(const float4 v0, const float4 v1, uint4& h, uint4& l) {
    h.x = pack_hi2(v0.x, v0.y, l.x);
    h.y = pack_hi2(v0.z, v0.w, l.y);
    h.z = pack_hi2(v1.x, v1.y, l.z);
    h.w = pack_hi2(v1.z, v1.w, l.w);
}

// ---------------------------------------------------------------------------
// Pre-kernels: global bf16 hi/lo images of src and W1[:, 512:]
// ---------------------------------------------------------------------------
__global__ __launch_bounds__(256) void k_convA(const float* __restrict__ src) {
    size_t u = (size_t)blockIdx.x * 256 + threadIdx.x;   // 8.39M units of 8 elems
    const float* p = src + u * 8;
    float4 v0 = *(const float4*)p;
    float4 v1 = *(const float4*)(p + 4);
    uint4 h, l;
    cvt8(v0, v1, h, l);
    *(uint4*)((char*)g_Ahi + u * 16) = h;
    *(uint4*)((char*)g_Alo + u * 16) = l;
}
__global__ __launch_bounds__(256) void k_convB(const float* __restrict__ W1) {
    int u = blockIdx.x * 256 + threadIdx.x;              // 32768 units
    int a = u >> 6, seg = u & 63;
    const float* p = W1 + (size_t)a * (DIN + DSRC) + DIN + seg * 8;
    float4 v0 = *(const float4*)p;
    float4 v1 = *(const float4*)(p + 4);
    uint4 h, l;
    cvt8(v0, v1, h, l);
    *(uint4*)((char*)g_Bhi + (size_t)(a * 512 + seg * 8) * 2) = h;
    *(uint4*)((char*)g_Blo + (size_t)(a * 512 + seg * 8) * 2) = l;
}

// ---------------------------------------------------------------------------
// Pre-kernel: g_q[b][a] = input[b,:] . W1[a, :512] + b1[a]
// ---------------------------------------------------------------------------
__global__ __launch_bounds__(256) void k_q(const float* __restrict__ inp,
                                           const float* __restrict__ W1,
                                           const float* __restrict__ b1) {
    int gw = blockIdx.x * 8 + (threadIdx.x >> 5);
    int lane = threadIdx.x & 31;
    int b = gw >> 9, a = gw & 511;
    const float* ip = inp + b * DIN;
    const float* wp = W1 + (size_t)a * (DIN + DSRC);
    float s = 0.f;
    #pragma unroll 4
    for (int k = lane; k < DIN; k += 32) s += ip[k] * wp[k];
    #pragma unroll
    for (int o = 16; o; o >>= 1) s += __shfl_xor_sync(0xFFFFFFFFu, s, o);
    if (lane == 0) g_q[b * DAL + a] = s + b1[a];
}

// ---------------------------------------------------------------------------
// Main HMMA kernel: cp.async 3-stage pipeline, SW64 64B rows, no conversions.
// CTA: M=128 tokens x N=128 aligns, K=512 in 16 chunks of 32.
// Grid (4 n-tiles fast, 1024 token-tiles slow) -> A tiles L2-reused.
// 8 warps: warp_m = wid&3 (32 rows), warp_n = wid>>2 (64 cols).
// D = Ahi.Bhi + Ahi.Blo + Alo.Bhi (fp32 accum in registers).
// ---------------------------------------------------------------------------
#define BUF_AH 0
#define BUF_AL 8192
#define BUF_BH 16384
#define BUF_BL 24576
#define STAGE_SZ 32768
#define S_W2   98304                      // 3 stages end here
#define S_RED  (S_W2 + 512)
#define SMEM_TOTAL (S_RED + 1024)         // 99840

__device__ __forceinline__ void issue_stage(uint32_t sb, int t0, int n0, int kc,
                                            int stage, int tid) {
    const uint32_t st = sb + stage * STAGE_SZ;
    const int u0 = tid, u1 = tid + 256;
    const int r0 = u0 >> 2, s0 = u0 & 3;
    const int r1 = u1 >> 2, s1 = u1 & 3;
    const uint32_t d0 = SW64((uint32_t)(r0 * 64 + s0 * 16));
    const uint32_t d1 = SW64((uint32_t)(r1 * 64 + s1 * 16));
    const size_t ga0 = (size_t)(t0 + r0) * DSRC + kc * 32 + s0 * 8;
    const size_t ga1 = (size_t)(t0 + r1) * DSRC + kc * 32 + s1 * 8;
    const size_t gb0 = (size_t)(n0 + r0) * DSRC + kc * 32 + s0 * 8;
    const size_t gb1 = (size_t)(n0 + r1) * DSRC + kc * 32 + s1 * 8;
    CP16(st + BUF_AH + d0, g_Ahi + ga0);
    CP16(st + BUF_AH + d1, g_Ahi + ga1);
    CP16(st + BUF_AL + d0, g_Alo + ga0);
    CP16(st + BUF_AL + d1, g_Alo + ga1);
    CP16(st + BUF_BH + d0, g_Bhi + gb0);
    CP16(st + BUF_BH + d1, g_Bhi + gb1);
    CP16(st + BUF_BL + d0, g_Blo + gb0);
    CP16(st + BUF_BL + d1, g_Blo + gb1);
    CP_COMMIT();
}

__global__ __launch_bounds__(256, 2) void k_main(const float* __restrict__ W2) {
    extern __shared__ __align__(16) char smem[];
    const uint32_t sb = smem_u32(smem);
    const int tid = threadIdx.x;
    const int lane = tid & 31;
    const int wid = tid >> 5;
    const int warp_m = wid & 3;
    const int warp_n = wid >> 2;
    const int n0 = blockIdx.x * 128;     // n-tile FAST -> A reuse in L2
    const int t0 = blockIdx.y * 128;

    float acc[2][8][4];
    #pragma unroll
    for (int mt = 0; mt < 2; mt++)
        #pragma unroll
        for (int nt = 0; nt < 8; nt++)
            #pragma unroll
            for (int c = 0; c < 4; c++) acc[mt][nt][c] = 0.f;

    if (tid < 128) ((float*)(smem + S_W2))[tid] = W2[n0 + tid];

    // Prologue: stages 0,1
    issue_stage(sb, t0, n0, 0, 0, tid);
    issue_stage(sb, t0, n0, 1, 1, tid);

    // ldmatrix lane-address components
    const uint32_t a_row = warp_m * 32 + (lane & 15);
    const uint32_t a_kadd = (lane >> 4) * 16;
    const uint32_t b_row = warp_n * 64 + (lane & 7) + ((lane >> 4) & 1) * 8;
    const uint32_t b_kadd = ((lane >> 3) & 1) * 16;

    for (int kc = 0; kc < 16; kc++) {
        if (kc == 15) CP_WAIT0(); else CP_WAIT1();
        __syncthreads();
        if (kc + 2 < 16) issue_stage(sb, t0, n0, kc + 2, (kc + 2) % 3, tid);

        const uint32_t st = sb + (kc % 3) * STAGE_SZ;
        #pragma unroll
        for (int ks = 0; ks < 2; ks++) {
            const uint32_t koff = ks * 32;
            uint32_t ahi[2][4], alo[2][4];
            #pragma unroll
            for (int mt = 0; mt < 2; mt++) {
                uint32_t off = (a_row + mt * 16) * 64 + koff + a_kadd;
                ldsm4(ahi[mt], st + BUF_AH + SW64(off));
                ldsm4(alo[mt], st + BUF_AL + SW64(off));
            }
            #pragma unroll
            for (int np = 0; np < 4; np++) {
                uint32_t off = (b_row + np * 16) * 64 + koff + b_kadd;
                uint32_t bh[4], bl[4];
                ldsm4(bh, st + BUF_BH + SW64(off));
                ldsm4(bl, st + BUF_BL + SW64(off));
                #pragma unroll
                for (int mt = 0; mt < 2; mt++) {
                    #pragma unroll
                    for (int sub = 0; sub < 2; sub++) {
                        float* d = acc[mt][np * 2 + sub];
                        mma_bf16(d, ahi[mt], &bh[sub * 2]);
                        mma_bf16(d, ahi[mt], &bl[sub * 2]);
                        mma_bf16(d, alo[mt], &bh[sub * 2]);
                    }
                }
            }
        }
    }
    __syncthreads();   // all compute done; stage smem reusable

    // Stage q[b][n0..n0+127] into smem overlay (pad-132 rows)
    float* qs = (float*)smem;
    #pragma unroll
    for (int i = 0; i < 8; i++) {
        int unit = tid + i * 256;         // 2048 float4 units
        int b = unit >> 5, c4 = unit & 31;
        float4 v = *(const float4*)(g_q + b * DAL + n0 + c4 * 4);
        float* d = qs + b * 132 + c4 * 4;
        d[0] = v.x; d[1] = v.y; d[2] = v.z; d[3] = v.w;
    }
    __syncthreads();

    // Epilogue: per-thread tanh + W2 dot, quad-reduce, cross-warp_n combine
    {
        const float* w2s = (const float*)(smem + S_W2);
        float* red = (float*)(smem + S_RED);
        float p[2][2] = {{0.f, 0.f}, {0.f, 0.f}};
        const int colq = 2 * (lane & 3);
        #pragma unroll
        for (int mt = 0; mt < 2; mt++) {
            #pragma unroll
            for (int nt = 0; nt < 8; nt++) {
                int nloc = warp_n * 64 + nt * 8 + colq;
                float w2a = w2s[nloc], w2b = w2s[nloc + 1];
                #pragma unroll
                for (int h = 0; h < 2; h++) {
                    int rowloc = warp_m * 32 + mt * 16 + h * 8 + (lane >> 2);
                    int b = rowloc & 63;
                    float q0 = qs[b * 132 + nloc];
                    float q1 = qs[b * 132 + nloc + 1];
                    p[mt][h] += w2a * tanhf(acc[mt][nt][h * 2 + 0] + q0)
                              + w2b * tanhf(acc[mt][nt][h * 2 + 1] + q1);
                }
            }
        }
        #pragma unroll
        for (int mt = 0; mt < 2; mt++)
            #pragma unroll
            for (int h = 0; h < 2; h++) {
                p[mt][h] += __shfl_xor_sync(0xFFFFFFFFu, p[mt][h], 1);
                p[mt][h] += __shfl_xor_sync(0xFFFFFFFFu, p[mt][h], 2);
            }
        if ((lane & 3) == 0) {
            #pragma unroll
            for (int mt = 0; mt < 2; mt++)
                #pragma unroll
                for (int h = 0; h < 2; h++) {
                    int rowloc = warp_m * 32 + mt * 16 + h * 8 + (lane >> 2);
                    red[rowloc * 2 + warp_n] = p[mt][h];
                }
        }
        __syncthreads();
        if (tid < 128) {
            int t = t0 + tid;
            g_part[blockIdx.x * NTOK + (t & 63) * SLEN + (t >> 6)] =
                red[tid * 2] + red[tid * 2 + 1];
        }
    }
}

// ---------------------------------------------------------------------------
// Softmax over S per batch; sums the 4 n-tile partials; attn -> out[CTX + s*B + b]
// ---------------------------------------------------------------------------
__global__ __launch_bounds__(256) void k_softmax(const unsigned char* __restrict__ mask,
                                                 float* __restrict__ out) {
    const int b = blockIdx.x;
    const int tid = threadIdx.x;
    __shared__ float red[256];
    const float* p0 = g_part + 0 * NTOK + b * SLEN;
    const float* p1 = g_part + 1 * NTOK + b * SLEN;
    const float* p2 = g_part + 2 * NTOK + b * SLEN;
    const float* p3 = g_part + 3 * NTOK + b * SLEN;

    float lmax = -INFINITY;
    for (int s = tid; s < SLEN; s += 256) {
        float v = mask[s * BATCH + b] ? -INFINITY : (p0[s] + p1[s] + p2[s] + p3[s]);
        lmax = fmaxf(lmax, v);
    }
    red[tid] = lmax; __syncthreads();
    for (int o = 128; o; o >>= 1) {
        if (tid < o) red[tid] = fmaxf(red[tid], red[tid + o]);
        __syncthreads();
    }
    float m = red[0]; __syncthreads();

    float lsum = 0.f;
    for (int s = tid; s < SLEN; s += 256) {
        float v = mask[s * BATCH + b] ? -INFINITY : (p0[s] + p1[s] + p2[s] + p3[s]);
        lsum += expf(v - m);
    }
    red[tid] = lsum; __syncthreads();
    for (int o = 128; o; o >>= 1) {
        if (tid < o) red[tid] += red[tid + o];
        __syncthreads();
    }
    float inv = 1.f / red[0];

    for (int s = tid; s < SLEN; s += 256) {
        float v = mask[s * BATCH + b] ? -INFINITY : (p0[s] + p1[s] + p2[s] + p3[s]);
        out[CTX_ELEMS + s * BATCH + b] = expf(v - m) * inv;
    }
}

// ---------------------------------------------------------------------------
// ctx[b, d] = sum_s attn[s, b] * src[s, b, d]   (split-S, atomic merge)
// ---------------------------------------------------------------------------
__global__ __launch_bounds__(256) void k_ctx(const float* __restrict__ src,
                                             float* __restrict__ out) {
    const int b = blockIdx.x;
    const int c = blockIdx.y;
    const int tid = threadIdx.x;
    const float* attn = out + CTX_ELEMS;

    float ax = 0.f, ay = 0.f;
    const int s_begin = c * (SLEN / 8);
    const int s_end = s_begin + (SLEN / 8);
    for (int s = s_begin; s < s_end; s += 2) {
        float a0 = attn[s * BATCH + b];
        float a1 = attn[(s + 1) * BATCH + b];
        float2 v0 = *reinterpret_cast<const float2*>(
            src + (size_t)(s * BATCH + b) * DSRC + tid * 2);
        float2 v1 = *reinterpret_cast<const float2*>(
            src + (size_t)((s + 1) * BATCH + b) * DSRC + tid * 2);
        ax += a0 * v0.x + a1 * v1.x;
        ay += a0 * v0.y + a1 * v1.y;
    }
    atomicAdd(&out[b * DSRC + tid * 2 + 0], ax);
    atomicAdd(&out[b * DSRC + tid * 2 + 1], ay);
}

// ---------------------------------------------------------------------------
extern "C" void kernel_launch(void* const* d_in, const int* in_sizes, int n_in,
                              void* d_out, int out_size) {
    const float* inp = (const float*)d_in[0];
    const float* src = (const float*)d_in[1];
    const unsigned char* mask = (const unsigned char*)d_in[2];
    const float* W1 = (const float*)d_in[3];
    const float* b1 = (const float*)d_in[4];
    const float* W2 = (const float*)d_in[5];
    float* out = (float*)d_out;

    cudaFuncSetAttribute(k_main, cudaFuncAttributeMaxDynamicSharedMemorySize, SMEM_TOTAL);

    cudaMemsetAsync(out, 0, CTX_ELEMS * sizeof(float), 0);

    k_convB<<<128, 256>>>(W1);
    k_convA<<<(int)((size_t)NTOK * DSRC / 8 / 256), 256>>>(src);
    k_q<<<4096, 256>>>(inp, W1, b1);

    dim3 gg(4, NTOK / 128);               // n-tile fast, token-tile slow
    k_main<<<gg, 256, SMEM_TOTAL>>>(W2);

    k_softmax<<<BATCH, 256>>>(mask, out);
    k_ctx<<<dim3(BATCH, 8), 256>>>(src, out);
}

// round 8
// speedup vs baseline: 4.0141x; 1.4636x over previous
#include <cuda_runtime.h>
#include <cuda_bf16.h>
#include <math.h>
#include <stdint.h>

#define SLEN 2048
#define BATCH 64
#define DIN 512
#define DSRC 512
#define DAL 512
#define NTOK (SLEN * BATCH)       // 131072
#define CTX_ELEMS (BATCH * DSRC)  // 32768

// ---------------------------------------------------------------------------
// Scratch (__device__ globals; no cudaMalloc allowed)
// ---------------------------------------------------------------------------
__device__ float g_q[BATCH * DAL];        // input@W1[:, :512]^T + b1
__device__ float g_part[4 * NTOK];        // per-n-tile partial scores [nt][b][s]
__device__ float g_Btf[DAL * DSRC];       // W1[:, 512:] pre-rounded to tf32 (RNA)

// ---------------------------------------------------------------------------
// Helpers
// ---------------------------------------------------------------------------
#define SW128(o) ((o) ^ (((o) >> 3) & 0x70))

__device__ __forceinline__ uint32_t smem_u32(const void* p) {
    uint32_t a;
    asm("{ .reg .u64 t; cvta.to.shared.u64 t, %1; cvt.u32.u64 %0, t; }" : "=r"(a) : "l"(p));
    return a;
}
#define CP16(dst, src) \
    asm volatile("cp.async.cg.shared.global [%0], [%1], 16;" :: "r"(dst), "l"(src))
#define CP_COMMIT() asm volatile("cp.async.commit_group;" ::: "memory")
#define CP_WAIT1() asm volatile("cp.async.wait_group 1;" ::: "memory")
#define CP_WAIT0() asm volatile("cp.async.wait_group 0;" ::: "memory")

__device__ __forceinline__ void ldsm4(uint32_t* r, uint32_t addr) {
    asm volatile("ldmatrix.sync.aligned.m8n8.x4.shared.b16 {%0,%1,%2,%3}, [%4];"
                 : "=r"(r[0]), "=r"(r[1]), "=r"(r[2]), "=r"(r[3]) : "r"(addr));
}
// D += A*B, tf32 m16n8k8. a: 4 regs (m16 x k8), b: 2 regs (k8 x n8)
__device__ __forceinline__ void mma_tf32(float* d, const uint32_t* a,
                                         uint32_t b0, uint32_t b1) {
    asm volatile("mma.sync.aligned.m16n8k8.row.col.f32.tf32.tf32.f32 "
                 "{%0,%1,%2,%3}, {%4,%5,%6,%7}, {%8,%9}, {%0,%1,%2,%3};"
                 : "+f"(d[0]), "+f"(d[1]), "+f"(d[2]), "+f"(d[3])
                 : "r"(a[0]), "r"(a[1]), "r"(a[2]), "r"(a[3]), "r"(b0), "r"(b1));
}
__device__ __forceinline__ float to_tf32(float x) {
    uint32_t o;
    asm("cvt.rna.tf32.f32 %0, %1;" : "=r"(o) : "f"(x));
    return __uint_as_float(o);
}

// ---------------------------------------------------------------------------
// Pre-kernel: g_Btf = tf32(W1[:, 512:])   (RNA rounding; 1MB image)
// ---------------------------------------------------------------------------
__global__ __launch_bounds__(256) void k_convB(const float* __restrict__ W1) {
    int u = blockIdx.x * 256 + threadIdx.x;     // 32768 units of 8 elems
    int a = u >> 6, seg = u & 63;
    const float* p = W1 + (size_t)a * (DIN + DSRC) + DIN + seg * 8;
    float* o = g_Btf + a * 512 + seg * 8;
    #pragma unroll
    for (int i = 0; i < 8; i++) o[i] = to_tf32(p[i]);
}

// ---------------------------------------------------------------------------
// Pre-kernel: g_q[b][a] = input[b,:] . W1[a, :512] + b1[a]
// ---------------------------------------------------------------------------
__global__ __launch_bounds__(256) void k_q(const float* __restrict__ inp,
                                           const float* __restrict__ W1,
                                           const float* __restrict__ b1) {
    int gw = blockIdx.x * 8 + (threadIdx.x >> 5);
    int lane = threadIdx.x & 31;
    int b = gw >> 9, a = gw & 511;
    const float* ip = inp + b * DIN;
    const float* wp = W1 + (size_t)a * (DIN + DSRC);
    float s = 0.f;
    #pragma unroll 4
    for (int k = lane; k < DIN; k += 32) s += ip[k] * wp[k];
    #pragma unroll
    for (int o = 16; o; o >>= 1) s += __shfl_xor_sync(0xFFFFFFFFu, s, o);
    if (lane == 0) g_q[b * DAL + a] = s + b1[a];
}

// ---------------------------------------------------------------------------
// Main TF32 HMMA kernel: single-pass, cp.async 3-stage pipeline, SW128 128B rows.
// CTA: M=128 tokens x N=128 aligns, K=512 in 16 chunks of 32.
// A = src raw fp32 (HW-truncated tf32), B = g_Btf (RNA tf32).
// 8 warps: warp_m = wid&3 (32 rows), warp_n = wid>>2 (64 cols).
// ldmatrix.x4 matrix order (by address-lane group):
//   A: m0 rows0-7/k0-3, m1 rows8-15/k0-3, m2 rows0-7/k4-7, m3 rows8-15/k4-7
//   B: m0 n0-7/k0-3,   m1 n0-7/k4-7,    m2 n8-15/k0-3,   m3 n8-15/k4-7
// => mma pairs: n0-7 uses (b[0], b[1]); n8-15 uses (b[2], b[3]).
// ---------------------------------------------------------------------------
#define BUF_A 0
#define BUF_B 16384
#define STAGE_SZ 32768
#define S_W2   98304
#define S_RED  (S_W2 + 512)
#define SMEM_TOTAL (S_RED + 1024)         // 99840

__device__ __forceinline__ void issue_stage(uint32_t sb, const float* __restrict__ src,
                                            int t0, int n0, int kc, int stage, int tid) {
    const uint32_t st = sb + stage * STAGE_SZ;
    // 1024 16B-units per buffer (128 rows x 8 segs); 4 per thread per buffer
    #pragma unroll
    for (int i = 0; i < 4; i++) {
        const int u = tid + i * 256;
        const int r = u >> 3, s = u & 7;
        const uint32_t d = SW128((uint32_t)(r * 128 + s * 16));
        CP16(st + BUF_A + d, src + (size_t)(t0 + r) * DSRC + kc * 32 + s * 4);
        CP16(st + BUF_B + d, g_Btf + (size_t)(n0 + r) * DSRC + kc * 32 + s * 4);
    }
    CP_COMMIT();
}

__global__ __launch_bounds__(256, 2) void k_main(const float* __restrict__ src,
                                                 const float* __restrict__ W2) {
    extern __shared__ __align__(16) char smem[];
    const uint32_t sb = smem_u32(smem);
    const int tid = threadIdx.x;
    const int lane = tid & 31;
    const int wid = tid >> 5;
    const int warp_m = wid & 3;
    const int warp_n = wid >> 2;
    const int n0 = blockIdx.x * 128;     // n-tile FAST -> A reuse in L2
    const int t0 = blockIdx.y * 128;

    float acc[2][8][4];
    #pragma unroll
    for (int mt = 0; mt < 2; mt++)
        #pragma unroll
        for (int nt = 0; nt < 8; nt++)
            #pragma unroll
            for (int c = 0; c < 4; c++) acc[mt][nt][c] = 0.f;

    if (tid < 128) ((float*)(smem + S_W2))[tid] = W2[n0 + tid];

    issue_stage(sb, src, t0, n0, 0, 0, tid);
    issue_stage(sb, src, t0, n0, 1, 1, tid);

    // ldmatrix lane-address components
    const uint32_t a_row = warp_m * 32 + (lane & 15);
    const uint32_t a_kadd = (lane >> 4) * 16;
    const uint32_t b_row = warp_n * 64 + (lane & 7) + ((lane >> 4) & 1) * 8;
    const uint32_t b_kadd = ((lane >> 3) & 1) * 16;

    for (int kc = 0; kc < 16; kc++) {
        if (kc == 15) CP_WAIT0(); else CP_WAIT1();
        __syncthreads();
        if (kc + 2 < 16) issue_stage(sb, src, t0, n0, kc + 2, (kc + 2) % 3, tid);

        const uint32_t st = sb + (kc % 3) * STAGE_SZ;
        #pragma unroll
        for (int ks = 0; ks < 4; ks++) {              // 4 x k8 per chunk
            const uint32_t koff = ks * 32;            // bytes (8 tf32)
            uint32_t a[2][4];
            #pragma unroll
            for (int mt = 0; mt < 2; mt++) {
                uint32_t off = (a_row + mt * 16) * 128 + koff + a_kadd;
                ldsm4(a[mt], st + BUF_A + SW128(off));
            }
            #pragma unroll
            for (int np = 0; np < 4; np++) {
                uint32_t off = (b_row + np * 16) * 128 + koff + b_kadd;
                uint32_t b[4];   // b0:n0-7/k0-3  b1:n0-7/k4-7  b2:n8-15/k0-3  b3:n8-15/k4-7
                ldsm4(b, st + BUF_B + SW128(off));
                #pragma unroll
                for (int mt = 0; mt < 2; mt++) {
                    mma_tf32(acc[mt][np * 2 + 0], a[mt], b[0], b[1]);
                    mma_tf32(acc[mt][np * 2 + 1], a[mt], b[2], b[3]);
                }
            }
        }
    }
    __syncthreads();   // compute done; stage smem reusable

    // Stage q[b][n0..n0+127] into smem overlay (pad-132 rows)
    float* qs = (float*)smem;
    #pragma unroll
    for (int i = 0; i < 8; i++) {
        int unit = tid + i * 256;         // 2048 float4 units
        int b = unit >> 5, c4 = unit & 31;
        float4 v = *(const float4*)(g_q + b * DAL + n0 + c4 * 4);
        float* d = qs + b * 132 + c4 * 4;
        d[0] = v.x; d[1] = v.y; d[2] = v.z; d[3] = v.w;
    }
    __syncthreads();

    // Epilogue: per-thread tanh + W2 dot, quad-reduce, cross-warp_n combine
    {
        const float* w2s = (const float*)(smem + S_W2);
        float* red = (float*)(smem + S_RED);
        float p[2][2] = {{0.f, 0.f}, {0.f, 0.f}};
        const int colq = 2 * (lane & 3);
        #pragma unroll
        for (int mt = 0; mt < 2; mt++) {
            #pragma unroll
            for (int nt = 0; nt < 8; nt++) {
                int nloc = warp_n * 64 + nt * 8 + colq;
                float w2a = w2s[nloc], w2b = w2s[nloc + 1];
                #pragma unroll
                for (int h = 0; h < 2; h++) {
                    int rowloc = warp_m * 32 + mt * 16 + h * 8 + (lane >> 2);
                    int b = rowloc & 63;
                    float q0 = qs[b * 132 + nloc];
                    float q1 = qs[b * 132 + nloc + 1];
                    p[mt][h] += w2a * tanhf(acc[mt][nt][h * 2 + 0] + q0)
                              + w2b * tanhf(acc[mt][nt][h * 2 + 1] + q1);
                }
            }
        }
        #pragma unroll
        for (int mt = 0; mt < 2; mt++)
            #pragma unroll
            for (int h = 0; h < 2; h++) {
                p[mt][h] += __shfl_xor_sync(0xFFFFFFFFu, p[mt][h], 1);
                p[mt][h] += __shfl_xor_sync(0xFFFFFFFFu, p[mt][h], 2);
            }
        if ((lane & 3) == 0) {
            #pragma unroll
            for (int mt = 0; mt < 2; mt++)
                #pragma unroll
                for (int h = 0; h < 2; h++) {
                    int rowloc = warp_m * 32 + mt * 16 + h * 8 + (lane >> 2);
                    red[rowloc * 2 + warp_n] = p[mt][h];
                }
        }
        __syncthreads();
        if (tid < 128) {
            int t = t0 + tid;
            g_part[blockIdx.x * NTOK + (t & 63) * SLEN + (t >> 6)] =
                red[tid * 2] + red[tid * 2 + 1];
        }
    }
}

// ---------------------------------------------------------------------------
// Softmax over S per batch; sums the 4 n-tile partials; attn -> out[CTX + s*B + b]
// ---------------------------------------------------------------------------
__global__ __launch_bounds__(256) void k_softmax(const unsigned char* __restrict__ mask,
                                                 float* __restrict__ out) {
    const int b = blockIdx.x;
    const int tid = threadIdx.x;
    __shared__ float red[256];
    const float* p0 = g_part + 0 * NTOK + b * SLEN;
    const float* p1 = g_part + 1 * NTOK + b * SLEN;
    const float* p2 = g_part + 2 * NTOK + b * SLEN;
    const float* p3 = g_part + 3 * NTOK + b * SLEN;

    float lmax = -INFINITY;
    for (int s = tid; s < SLEN; s += 256) {
        float v = mask[s * BATCH + b] ? -INFINITY : (p0[s] + p1[s] + p2[s] + p3[s]);
        lmax = fmaxf(lmax, v);
    }
    red[tid] = lmax; __syncthreads();
    for (int o = 128; o; o >>= 1) {
        if (tid < o) red[tid] = fmaxf(red[tid], red[tid + o]);
        __syncthreads();
    }
    float m = red[0]; __syncthreads();

    float lsum = 0.f;
    for (int s = tid; s < SLEN; s += 256) {
        float v = mask[s * BATCH + b] ? -INFINITY : (p0[s] + p1[s] + p2[s] + p3[s]);
        lsum += expf(v - m);
    }
    red[tid] = lsum; __syncthreads();
    for (int o = 128; o; o >>= 1) {
        if (tid < o) red[tid] += red[tid + o];
        __syncthreads();
    }
    float inv = 1.f / red[0];

    for (int s = tid; s < SLEN; s += 256) {
        float v = mask[s * BATCH + b] ? -INFINITY : (p0[s] + p1[s] + p2[s] + p3[s]);
        out[CTX_ELEMS + s * BATCH + b] = expf(v - m) * inv;
    }
}

// ---------------------------------------------------------------------------
// ctx[b, d] = sum_s attn[s, b] * src[s, b, d]   (split-S, atomic merge)
// ---------------------------------------------------------------------------
__global__ __launch_bounds__(256) void k_ctx(const float* __restrict__ src,
                                             float* __restrict__ out) {
    const int b = blockIdx.x;
    const int c = blockIdx.y;
    const int tid = threadIdx.x;
    const float* attn = out + CTX_ELEMS;

    float ax = 0.f, ay = 0.f;
    const int s_begin = c * (SLEN / 8);
    const int s_end = s_begin + (SLEN / 8);
    for (int s = s_begin; s < s_end; s += 2) {
        float a0 = attn[s * BATCH + b];
        float a1 = attn[(s + 1) * BATCH + b];
        float2 v0 = *reinterpret_cast<const float2*>(
            src + (size_t)(s * BATCH + b) * DSRC + tid * 2);
        float2 v1 = *reinterpret_cast<const float2*>(
            src + (size_t)((s + 1) * BATCH + b) * DSRC + tid * 2);
        ax += a0 * v0.x + a1 * v1.x;
        ay += a0 * v0.y + a1 * v1.y;
    }
    atomicAdd(&out[b * DSRC + tid * 2 + 0], ax);
    atomicAdd(&out[b * DSRC + tid * 2 + 1], ay);
}

// ---------------------------------------------------------------------------
extern "C" void kernel_launch(void* const* d_in, const int* in_sizes, int n_in,
                              void* d_out, int out_size) {
    const float* inp = (const float*)d_in[0];
    const float* src = (const float*)d_in[1];
    const unsigned char* mask = (const unsigned char*)d_in[2];
    const float* W1 = (const float*)d_in[3];
    const float* b1 = (const float*)d_in[4];
    const float* W2 = (const float*)d_in[5];
    float* out = (float*)d_out;

    cudaFuncSetAttribute(k_main, cudaFuncAttributeMaxDynamicSharedMemorySize, SMEM_TOTAL);

    cudaMemsetAsync(out, 0, CTX_ELEMS * sizeof(float), 0);

    k_convB<<<128, 256>>>(W1);
    k_q<<<4096, 256>>>(inp, W1, b1);

    dim3 gg(4, NTOK / 128);               // n-tile fast, token-tile slow
    k_main<<<gg, 256, SMEM_TOTAL>>>(src, W2);

    k_softmax<<<BATCH, 256>>>(mask, out);
    k_ctx<<<dim3(BATCH, 8), 256>>>(src, out);
}